// round 14
// baseline (speedup 1.0000x reference)
#include <cuda_runtime.h>
#include <cuda_bf16.h>
#include <math.h>
#include <stdint.h>

#define NROWS 131072
#define QKV_STRIDE 25165824ll

__device__ __nv_bfloat16 g_qkvh[3ll * 25165824];
__device__ __nv_bfloat16 g_xbf[25165824];
__device__ __nv_bfloat16 g_att[25165824];
__device__ float g_x1[25165824];
__device__ __nv_bfloat16 g_x1bf[25165824];
__device__ __nv_bfloat16 g_h[100663296ll];
__device__ __nv_bfloat16 g_wbf[442368];

__device__ __forceinline__ int map_row(int r) {
    int wid = r >> 6, n = r & 63;
    int b = wid >> 6, w = wid & 63;
    int h  = ((w >> 3) << 3) + (n >> 3);
    int ww = ((w & 7) << 3) + (n & 7);
    int ho = (h + 4) & 63, wo = (ww + 4) & 63;
    return (b << 12) + (ho << 6) + wo;
}
__device__ __forceinline__ int region(int x) { return x < 56 ? 0 : (x < 60 ? 1 : 2); }

__device__ __forceinline__ void cpa16(unsigned s, const void* g) {
    asm volatile("cp.async.cg.shared.global [%0], [%1], 16;" :: "r"(s), "l"(g));
}
#define CP_COMMIT() asm volatile("cp.async.commit_group;")
#define CP_WAIT2()  asm volatile("cp.async.wait_group 2;")
#define CP_WAIT0()  asm volatile("cp.async.wait_group 0;" ::: "memory")

__device__ __forceinline__ void ldsm4(unsigned* r, unsigned a) {
    asm volatile("ldmatrix.sync.aligned.m8n8.x4.shared.b16 {%0,%1,%2,%3}, [%4];"
        : "=r"(r[0]), "=r"(r[1]), "=r"(r[2]), "=r"(r[3]) : "r"(a));
}
__device__ __forceinline__ void ldsm4t(unsigned* r, unsigned a) {
    asm volatile("ldmatrix.sync.aligned.m8n8.x4.trans.shared.b16 {%0,%1,%2,%3}, [%4];"
        : "=r"(r[0]), "=r"(r[1]), "=r"(r[2]), "=r"(r[3]) : "r"(a));
}
__device__ __forceinline__ void mma_bf16(float* d, const unsigned* a, const unsigned* b) {
    asm volatile(
        "mma.sync.aligned.m16n8k16.row.col.f32.bf16.bf16.f32 "
        "{%0,%1,%2,%3}, {%4,%5,%6,%7}, {%8,%9}, {%0,%1,%2,%3};"
        : "+f"(d[0]), "+f"(d[1]), "+f"(d[2]), "+f"(d[3])
        : "r"(a[0]), "r"(a[1]), "r"(a[2]), "r"(a[3]), "r"(b[0]), "r"(b[1]));
}
__device__ __forceinline__ void mma_bf16_2(float* d, const unsigned* a, unsigned b0, unsigned b1) {
    asm volatile(
        "mma.sync.aligned.m16n8k16.row.col.f32.bf16.bf16.f32 "
        "{%0,%1,%2,%3}, {%4,%5,%6,%7}, {%8,%9}, {%0,%1,%2,%3};"
        : "+f"(d[0]), "+f"(d[1]), "+f"(d[2]), "+f"(d[3])
        : "r"(a[0]), "r"(a[1]), "r"(a[2]), "r"(a[3]), "r"(b0), "r"(b1));
}
__device__ __forceinline__ unsigned pack2(float e, float o) {
    __nv_bfloat162 h = __floats2bfloat162_rn(e, o);
    return *reinterpret_cast<unsigned*>(&h);
}

template<int MODE, int NCOLS>
__device__ __forceinline__ void epi_store(
    int r, int c, float v, const float* __restrict__ bias,
    const float* __restrict__ aux, float* __restrict__ outf,
    __nv_bfloat16* __restrict__ outh)
{
    v += bias[c];
    if (MODE == 0) {
        int which = c / 192, rem = c % 192;
        int head = rem >> 5, hd = rem & 31;
        if (which == 0) v *= 0.17677669529663689f;
        int wid = r >> 6, n = r & 63;
        outh[(long)which * QKV_STRIDE + (((long)(wid * 6 + head) * 64 + n) * 32 + hd)] =
            __float2bfloat16(v);
    } else if (MODE == 1) {
        long o = (long)map_row(r) * 192 + c;
        float s = aux[o] + v;
        outf[o] = s;
        outh[o] = __float2bfloat16(s);
    } else if (MODE == 2) {
        outh[(long)r * NCOLS + c] =
            __float2bfloat16(0.5f * v * (1.0f + erff(v * 0.7071067811865476f)));
    } else {
        long o = (long)r * NCOLS + c;
        outf[o] = aux[o] + v;
    }
}

// ---------------------------------------------------------------------------
// bf16 mma.sync GEMM: block 128 x NTILE, BK=32, 4-stage cp.async pipeline,
// 8 warps (4M x 2N), warp tile 32 x NTILE/2. nOff = column offset for
// split-N launches.
// ---------------------------------------------------------------------------
#define A_STAGE 10240   // 128 rows * 80B

template<int MODE, int K, int NCOLS, int NTILE>
__global__ __launch_bounds__(256) void gemm_bf16(
    const __nv_bfloat16* __restrict__ A, const __nv_bfloat16* __restrict__ Bm,
    const float* __restrict__ bias, const float* __restrict__ aux,
    float* __restrict__ outf, __nv_bfloat16* __restrict__ outh, int nOff)
{
    constexpr int BROW = 2 * NTILE + 16;
    constexpr int B_STAGE = 32 * BROW;
    constexpr int G  = NTILE / 32;
    constexpr int NI = NTILE / 16;
    constexpr int CPT = NTILE / 64;

    extern __shared__ char smem_raw[];
    const unsigned aBase = (unsigned)__cvta_generic_to_shared(smem_raw);
    const unsigned bBase = aBase + 4 * A_STAGE;

    const int mBase = blockIdx.y * 128;
    const int nBase = blockIdx.x * NTILE + nOff;
    const int t = threadIdx.x;
    const int lane = t & 31, warp = t >> 5;
    const int warpM = warp >> 1, warpN = warp & 1;
    const int lq = lane >> 2, lr = lane & 3;

    const int ar = t >> 2;
    const int ac = (t & 3) * 8;
    long row1 = (MODE == 0) ? (long)map_row(mBase + ar)      : (long)(mBase + ar);
    long row2 = (MODE == 0) ? (long)map_row(mBase + ar + 64) : (long)(mBase + ar + 64);
    const __nv_bfloat16* Ap1 = A + row1 * K + ac;
    const __nv_bfloat16* Ap2 = A + row2 * K + ac;
    const unsigned sA1 = aBase + ar * 80 + (t & 3) * 16;
    const unsigned sA2 = sA1 + 64 * 80;
    const int bk = t >> 3;
    const __nv_bfloat16* Bp = Bm + (long)bk * NCOLS + nBase + (t & 7) * 8;
    const unsigned sB = bBase + bk * BROW + (t & 7) * 16;

    float acc[2][NI][4];
    #pragma unroll
    for (int mi = 0; mi < 2; mi++)
        #pragma unroll
        for (int ni = 0; ni < NI; ni++)
            #pragma unroll
            for (int e = 0; e < 4; e++) acc[mi][ni][e] = 0.f;

    const int NK = K / 32;
    #pragma unroll
    for (int s = 0; s < 3; s++) {
        cpa16(sA1 + s * A_STAGE, Ap1 + s * 32);
        cpa16(sA2 + s * A_STAGE, Ap2 + s * 32);
        #pragma unroll
        for (int cc = 0; cc < CPT; cc++)
            cpa16(sB + s * B_STAGE + cc * 128, Bp + (long)s * 32 * NCOLS + cc * 64);
        CP_COMMIT();
    }

    for (int kt = 0; kt < NK; kt++) {
        const int s = kt & 3;
        CP_WAIT2();
        __syncthreads();
        if (kt + 3 < NK) {
            const int s2 = (kt + 3) & 3;
            cpa16(sA1 + s2 * A_STAGE, Ap1 + (kt + 3) * 32);
            cpa16(sA2 + s2 * A_STAGE, Ap2 + (kt + 3) * 32);
            #pragma unroll
            for (int cc = 0; cc < CPT; cc++)
                cpa16(sB + s2 * B_STAGE + cc * 128,
                      Bp + (long)(kt + 3) * 32 * NCOLS + cc * 64);
        }
        CP_COMMIT();

        const unsigned as0 = aBase + s * A_STAGE;
        const unsigned bs0 = bBase + s * B_STAGE;
        #pragma unroll
        for (int k16 = 0; k16 < 2; k16++) {
            unsigned af[2][4], bq[G][4];
            #pragma unroll
            for (int mi = 0; mi < 2; mi++)
                ldsm4(af[mi], as0 + (warpM * 32 + mi * 16 + (lane & 15)) * 80
                              + k16 * 32 + (lane >> 4) * 16);
            #pragma unroll
            for (int g = 0; g < G; g++)
                ldsm4t(bq[g], bs0 + (k16 * 16 + (lane & 15)) * BROW
                              + (warpN * (NTILE / 2) + g * 16 + ((lane >> 4) << 3)) * 2);
            #pragma unroll
            for (int mi = 0; mi < 2; mi++)
                #pragma unroll
                for (int ni = 0; ni < NI; ni++)
                    mma_bf16(acc[mi][ni], af[mi], &bq[ni >> 1][(ni & 1) * 2]);
        }
    }

    #pragma unroll
    for (int mi = 0; mi < 2; mi++) {
        int r0 = mBase + warpM * 32 + mi * 16 + lq;
        #pragma unroll
        for (int ni = 0; ni < NI; ni++) {
            int c0 = nBase + warpN * (NTILE / 2) + ni * 8 + lr * 2;
            epi_store<MODE, NCOLS>(r0,     c0,     acc[mi][ni][0], bias, aux, outf, outh);
            epi_store<MODE, NCOLS>(r0,     c0 + 1, acc[mi][ni][1], bias, aux, outf, outh);
            epi_store<MODE, NCOLS>(r0 + 8, c0,     acc[mi][ni][2], bias, aux, outf, outh);
            epi_store<MODE, NCOLS>(r0 + 8, c0 + 1, acc[mi][ni][3], bias, aux, outf, outh);
        }
    }
}

// ---------------------------------------------------------------------------
__global__ void f2bf(const float* __restrict__ in, __nv_bfloat16* __restrict__ out, int n) {
    int i = (blockIdx.x * blockDim.x + threadIdx.x) * 4;
    if (i >= n) return;
    float4 v = *(const float4*)(in + i);
    *(__nv_bfloat162*)(out + i)     = __floats2bfloat162_rn(v.x, v.y);
    *(__nv_bfloat162*)(out + i + 2) = __floats2bfloat162_rn(v.z, v.w);
}

// ---------------------------------------------------------------------------
// Tensor-core attention (unchanged from round 13).
// ---------------------------------------------------------------------------
__global__ __launch_bounds__(128) void attn_kernel(
    const float* __restrict__ rpb, __nv_bfloat16* __restrict__ out)
{
    __shared__ __align__(16) __nv_bfloat16 Qs[64 * 40];
    __shared__ __align__(16) __nv_bfloat16 Ks[64 * 40];
    __shared__ __align__(16) __nv_bfloat16 Vs[64 * 40];

    const int bh = blockIdx.x;
    const int wid = bh / 6, head = bh - wid * 6;
    const int w = wid & 63;
    const int t = threadIdx.x, lane = t & 31, warp = t >> 5;
    const int lq = lane >> 2, lr = lane & 3;

    const unsigned qA = (unsigned)__cvta_generic_to_shared(Qs);
    const unsigned kA = (unsigned)__cvta_generic_to_shared(Ks);
    const unsigned vA = (unsigned)__cvta_generic_to_shared(Vs);
    const __nv_bfloat16* qb = g_qkvh + (long)bh * 2048;

    #pragma unroll
    for (int c = t; c < 256; c += 128) {
        int row = c >> 2, o = c & 3;
        unsigned so = row * 80 + o * 16;
        const __nv_bfloat16* go = qb + row * 32 + o * 8;
        cpa16(qA + so, go);
        cpa16(kA + so, go + QKV_STRIDE);
        cpa16(vA + so, go + 2 * QKV_STRIDE);
    }
    CP_COMMIT();
    CP_WAIT0();
    __syncthreads();

    float sc[8][4];
    #pragma unroll
    for (int ni = 0; ni < 8; ni++)
        #pragma unroll
        for (int e = 0; e < 4; e++) sc[ni][e] = 0.f;

    unsigned af[2][4];
    #pragma unroll
    for (int kc = 0; kc < 2; kc++)
        ldsm4(af[kc], qA + (warp * 16 + (lane & 15)) * 80 + kc * 32 + (lane >> 4) * 16);
    #pragma unroll
    for (int kc = 0; kc < 2; kc++) {
        unsigned bq[4][4];
        #pragma unroll
        for (int g = 0; g < 4; g++)
            ldsm4(bq[g], kA + (g * 16 + (lane & 15)) * 80 + kc * 32 + (lane >> 4) * 16);
        #pragma unroll
        for (int ni = 0; ni < 8; ni++)
            mma_bf16_2(sc[ni], af[kc], bq[ni >> 1][ni & 1], bq[ni >> 1][2 + (ni & 1)]);
    }

    const int hb = (w >> 3) << 3, wbx = (w & 7) << 3;
    const int r0 = warp * 16 + lq, r1 = r0 + 8;
    const int rh0 = r0 >> 3, rw0 = r0 & 7, rh1 = r1 >> 3, rw1 = r1 & 7;
    const int reg0 = region(hb + rh0) * 3 + region(wbx + rw0);
    const int reg1 = region(hb + rh1) * 3 + region(wbx + rw1);
    const int base0 = ((rh0 + 7) * 15 + rw0 + 7) * 6 + head;
    const int base1 = ((rh1 + 7) * 15 + rw1 + 7) * 6 + head;

    float mx0 = -1e30f, mx1 = -1e30f;
    #pragma unroll
    for (int ni = 0; ni < 8; ni++) {
        #pragma unroll
        for (int e = 0; e < 2; e++) {
            int col = ni * 8 + 2 * lr + e;
            int ch = col >> 3, cw = col & 7;
            int cOff = (ch * 15 + cw) * 6;
            int regC = region(hb + ch) * 3 + region(wbx + cw);
            float v0 = sc[ni][e]     + __ldg(rpb + base0 - cOff) + (regC != reg0 ? -100.f : 0.f);
            float v1 = sc[ni][2 + e] + __ldg(rpb + base1 - cOff) + (regC != reg1 ? -100.f : 0.f);
            sc[ni][e] = v0; sc[ni][2 + e] = v1;
            mx0 = fmaxf(mx0, v0); mx1 = fmaxf(mx1, v1);
        }
    }
    mx0 = fmaxf(mx0, __shfl_xor_sync(0xffffffffu, mx0, 1));
    mx0 = fmaxf(mx0, __shfl_xor_sync(0xffffffffu, mx0, 2));
    mx1 = fmaxf(mx1, __shfl_xor_sync(0xffffffffu, mx1, 1));
    mx1 = fmaxf(mx1, __shfl_xor_sync(0xffffffffu, mx1, 2));

    float s0 = 0.f, s1 = 0.f;
    #pragma unroll
    for (int ni = 0; ni < 8; ni++) {
        #pragma unroll
        for (int e = 0; e < 2; e++) {
            float e0 = __expf(sc[ni][e] - mx0);
            float e1 = __expf(sc[ni][2 + e] - mx1);
            sc[ni][e] = e0; sc[ni][2 + e] = e1;
            s0 += e0; s1 += e1;
        }
    }
    s0 += __shfl_xor_sync(0xffffffffu, s0, 1);
    s0 += __shfl_xor_sync(0xffffffffu, s0, 2);
    s1 += __shfl_xor_sync(0xffffffffu, s1, 1);
    s1 += __shfl_xor_sync(0xffffffffu, s1, 2);
    const float inv0 = 1.f / s0, inv1 = 1.f / s1;

    unsigned pa[4][4];
    #pragma unroll
    for (int kc2 = 0; kc2 < 4; kc2++) {
        pa[kc2][0] = pack2(sc[2 * kc2][0],     sc[2 * kc2][1]);
        pa[kc2][1] = pack2(sc[2 * kc2][2],     sc[2 * kc2][3]);
        pa[kc2][2] = pack2(sc[2 * kc2 + 1][0], sc[2 * kc2 + 1][1]);
        pa[kc2][3] = pack2(sc[2 * kc2 + 1][2], sc[2 * kc2 + 1][3]);
    }
    float o4[4][4];
    #pragma unroll
    for (int nf = 0; nf < 4; nf++)
        #pragma unroll
        for (int e = 0; e < 4; e++) o4[nf][e] = 0.f;
    #pragma unroll
    for (int kc2 = 0; kc2 < 4; kc2++) {
        unsigned bv[2][4];
        #pragma unroll
        for (int g2 = 0; g2 < 2; g2++)
            ldsm4t(bv[g2], vA + (kc2 * 16 + (lane & 15)) * 80
                           + (g2 * 16 + ((lane >> 4) << 3)) * 2);
        #pragma unroll
        for (int nf = 0; nf < 4; nf++)
            mma_bf16(o4[nf], pa[kc2], &bv[nf >> 1][2 * (nf & 1)]);
    }

    const long grow = (long)(wid * 64 + r0);
    #pragma unroll
    for (int nf = 0; nf < 4; nf++) {
        int col = head * 32 + nf * 8 + 2 * lr;
        *(__nv_bfloat162*)(out + grow * 192 + col) =
            __floats2bfloat162_rn(o4[nf][0] * inv0, o4[nf][1] * inv0);
        *(__nv_bfloat162*)(out + (grow + 8) * 192 + col) =
            __floats2bfloat162_rn(o4[nf][2] * inv1, o4[nf][3] * inv1);
    }
}

// ---------------------------------------------------------------------------
extern "C" void kernel_launch(void* const* d_in, const int* in_sizes, int n_in,
                              void* d_out, int out_size)
{
    const float* x      = (const float*)d_in[0];
    const float* rpb    = (const float*)d_in[1];
    const float* qkv_w  = (const float*)d_in[2];
    const float* qkv_b  = (const float*)d_in[3];
    const float* proj_w = (const float*)d_in[4];
    const float* proj_b = (const float*)d_in[5];
    const float* fc1_w  = (const float*)d_in[6];
    const float* fc1_b  = (const float*)d_in[7];
    const float* fc2_w  = (const float*)d_in[8];
    const float* fc2_b  = (const float*)d_in[9];
    float* out = (float*)d_out;

    float *x1;
    __nv_bfloat16 *qkvh, *xbf, *att, *x1bf, *h, *wbf;
    cudaGetSymbolAddress((void**)&qkvh, g_qkvh);
    cudaGetSymbolAddress((void**)&xbf,  g_xbf);
    cudaGetSymbolAddress((void**)&att,  g_att);
    cudaGetSymbolAddress((void**)&x1,   g_x1);
    cudaGetSymbolAddress((void**)&x1bf, g_x1bf);
    cudaGetSymbolAddress((void**)&h,    g_h);
    cudaGetSymbolAddress((void**)&wbf,  g_wbf);

    constexpr int SM64  = 4 * (A_STAGE + 32 * 144);   // 59392
    constexpr int SM128 = 4 * (A_STAGE + 32 * 272);   // 75776
    cudaFuncSetAttribute(gemm_bf16<0, 192, 576, 128>, cudaFuncAttributeMaxDynamicSharedMemorySize, SM128);
    cudaFuncSetAttribute(gemm_bf16<0, 192, 576, 64>,  cudaFuncAttributeMaxDynamicSharedMemorySize, SM64);
    cudaFuncSetAttribute(gemm_bf16<1, 192, 192, 128>, cudaFuncAttributeMaxDynamicSharedMemorySize, SM128);
    cudaFuncSetAttribute(gemm_bf16<1, 192, 192, 64>,  cudaFuncAttributeMaxDynamicSharedMemorySize, SM64);
    cudaFuncSetAttribute(gemm_bf16<2, 192, 768, 128>, cudaFuncAttributeMaxDynamicSharedMemorySize, SM128);
    cudaFuncSetAttribute(gemm_bf16<3, 768, 192, 128>, cudaFuncAttributeMaxDynamicSharedMemorySize, SM128);
    cudaFuncSetAttribute(gemm_bf16<3, 768, 192, 64>,  cudaFuncAttributeMaxDynamicSharedMemorySize, SM64);

    f2bf<<<25165824 / 4 / 256, 256>>>(x, xbf, 25165824);
    f2bf<<<(110592 / 4 + 255) / 256, 256>>>(qkv_w,  wbf,          110592);
    f2bf<<<(36864  / 4 + 255) / 256, 256>>>(proj_w, wbf + 110592, 36864);
    f2bf<<<(147456 / 4 + 255) / 256, 256>>>(fc1_w,  wbf + 147456, 147456);
    f2bf<<<(147456 / 4 + 255) / 256, 256>>>(fc2_w,  wbf + 294912, 147456);

    // QKV: cols [0,512) at NTILE=128, [512,576) at NTILE=64
    gemm_bf16<0, 192, 576, 128><<<dim3(4, 1024), 256, SM128>>>(xbf, wbf, qkv_b, nullptr, nullptr, qkvh, 0);
    gemm_bf16<0, 192, 576, 64><<<dim3(1, 1024), 256, SM64>>>(xbf, wbf, qkv_b, nullptr, nullptr, qkvh, 512);
    attn_kernel<<<12288, 128>>>(rpb, att);
    // proj: cols [0,128) + [128,192)
    gemm_bf16<1, 192, 192, 128><<<dim3(1, 1024), 256, SM128>>>(att, wbf + 110592, proj_b, x, x1, x1bf, 0);
    gemm_bf16<1, 192, 192, 64><<<dim3(1, 1024), 256, SM64>>>(att, wbf + 110592, proj_b, x, x1, x1bf, 128);
    // fc1: all at NTILE=128
    gemm_bf16<2, 192, 768, 128><<<dim3(6, 1024), 256, SM128>>>(x1bf, wbf + 147456, fc1_b, nullptr, nullptr, h, 0);
    // fc2: cols [0,128) + [128,192)
    gemm_bf16<3, 768, 192, 128><<<dim3(1, 1024), 256, SM128>>>(h, wbf + 294912, fc2_b, x1, out, nullptr, 0);
    gemm_bf16<3, 768, 192, 64><<<dim3(1, 1024), 256, SM64>>>(h, wbf + 294912, fc2_b, x1, out, nullptr, 128);
}

// round 15
// speedup vs baseline: 1.0841x; 1.0841x over previous
#include <cuda_runtime.h>
#include <cuda_bf16.h>
#include <math.h>
#include <stdint.h>

#define NROWS 131072
#define QKV_STRIDE 25165824ll

__device__ __nv_bfloat16 g_qkvh[3ll * 25165824];
__device__ __nv_bfloat16 g_xbf[25165824];
__device__ __nv_bfloat16 g_att[25165824];
__device__ float g_x1[25165824];
__device__ __nv_bfloat16 g_x1bf[25165824];
__device__ __nv_bfloat16 g_h[100663296ll];
__device__ __nv_bfloat16 g_wbf[442368];

__device__ __forceinline__ int map_row(int r) {
    int wid = r >> 6, n = r & 63;
    int b = wid >> 6, w = wid & 63;
    int h  = ((w >> 3) << 3) + (n >> 3);
    int ww = ((w & 7) << 3) + (n & 7);
    int ho = (h + 4) & 63, wo = (ww + 4) & 63;
    return (b << 12) + (ho << 6) + wo;
}
__device__ __forceinline__ int region(int x) { return x < 56 ? 0 : (x < 60 ? 1 : 2); }

__device__ __forceinline__ void cpa16(unsigned s, const void* g) {
    asm volatile("cp.async.cg.shared.global [%0], [%1], 16;" :: "r"(s), "l"(g));
}
#define CP_COMMIT() asm volatile("cp.async.commit_group;")
#define CP_WAIT0()  asm volatile("cp.async.wait_group 0;" ::: "memory")

__device__ __forceinline__ void ldsm4(unsigned* r, unsigned a) {
    asm volatile("ldmatrix.sync.aligned.m8n8.x4.shared.b16 {%0,%1,%2,%3}, [%4];"
        : "=r"(r[0]), "=r"(r[1]), "=r"(r[2]), "=r"(r[3]) : "r"(a));
}
__device__ __forceinline__ void ldsm4t(unsigned* r, unsigned a) {
    asm volatile("ldmatrix.sync.aligned.m8n8.x4.trans.shared.b16 {%0,%1,%2,%3}, [%4];"
        : "=r"(r[0]), "=r"(r[1]), "=r"(r[2]), "=r"(r[3]) : "r"(a));
}
__device__ __forceinline__ void mma_bf16(float* d, const unsigned* a, const unsigned* b) {
    asm volatile(
        "mma.sync.aligned.m16n8k16.row.col.f32.bf16.bf16.f32 "
        "{%0,%1,%2,%3}, {%4,%5,%6,%7}, {%8,%9}, {%0,%1,%2,%3};"
        : "+f"(d[0]), "+f"(d[1]), "+f"(d[2]), "+f"(d[3])
        : "r"(a[0]), "r"(a[1]), "r"(a[2]), "r"(a[3]), "r"(b[0]), "r"(b[1]));
}
__device__ __forceinline__ void mma_bf16_2(float* d, const unsigned* a, unsigned b0, unsigned b1) {
    asm volatile(
        "mma.sync.aligned.m16n8k16.row.col.f32.bf16.bf16.f32 "
        "{%0,%1,%2,%3}, {%4,%5,%6,%7}, {%8,%9}, {%0,%1,%2,%3};"
        : "+f"(d[0]), "+f"(d[1]), "+f"(d[2]), "+f"(d[3])
        : "r"(a[0]), "r"(a[1]), "r"(a[2]), "r"(a[3]), "r"(b0), "r"(b1));
}
__device__ __forceinline__ unsigned pack2(float e, float o) {
    __nv_bfloat162 h = __floats2bfloat162_rn(e, o);
    return *reinterpret_cast<unsigned*>(&h);
}

template<int MODE, int NCOLS>
__device__ __forceinline__ void epi_store(
    int r, int c, float v, const float* __restrict__ bias,
    const float* __restrict__ aux, float* __restrict__ outf,
    __nv_bfloat16* __restrict__ outh)
{
    v += bias[c];
    if (MODE == 0) {
        int which = c / 192, rem = c % 192;
        int head = rem >> 5, hd = rem & 31;
        if (which == 0) v *= 0.17677669529663689f;
        int wid = r >> 6, n = r & 63;
        outh[(long)which * QKV_STRIDE + (((long)(wid * 6 + head) * 64 + n) * 32 + hd)] =
            __float2bfloat16(v);
    } else if (MODE == 1) {
        long o = (long)map_row(r) * 192 + c;
        float s = aux[o] + v;
        outf[o] = s;
        outh[o] = __float2bfloat16(s);
    } else if (MODE == 2) {
        outh[(long)r * NCOLS + c] =
            __float2bfloat16(0.5f * v * (1.0f + erff(v * 0.7071067811865476f)));
    } else {
        long o = (long)r * NCOLS + c;
        outf[o] = aux[o] + v;
    }
}

// ---------------------------------------------------------------------------
// bf16 mma.sync GEMM: block 128 x NTILE, BK=32, STAGES-deep cp.async pipeline,
// 8 warps (4M x 2N), warp tile 32 x NTILE/2.
// ---------------------------------------------------------------------------
#define A_STAGE 10240   // 128 rows * 80B

template<int MODE, int K, int NCOLS, int NTILE, int STAGES>
__global__ __launch_bounds__(256) void gemm_bf16(
    const __nv_bfloat16* __restrict__ A, const __nv_bfloat16* __restrict__ Bm,
    const float* __restrict__ bias, const float* __restrict__ aux,
    float* __restrict__ outf, __nv_bfloat16* __restrict__ outh)
{
    constexpr int BROW = 2 * NTILE + 16;
    constexpr int B_STAGE = 32 * BROW;
    constexpr int G  = NTILE / 32;
    constexpr int NI = NTILE / 16;
    constexpr int CPT = NTILE / 64;

    extern __shared__ char smem_raw[];
    const unsigned aBase = (unsigned)__cvta_generic_to_shared(smem_raw);
    const unsigned bBase = aBase + STAGES * A_STAGE;

    const int mBase = blockIdx.y * 128;
    const int nBase = blockIdx.x * NTILE;
    const int t = threadIdx.x;
    const int lane = t & 31, warp = t >> 5;
    const int warpM = warp >> 1, warpN = warp & 1;
    const int lq = lane >> 2, lr = lane & 3;

    const int ar = t >> 2;
    const int ac = (t & 3) * 8;
    long row1 = (MODE == 0) ? (long)map_row(mBase + ar)      : (long)(mBase + ar);
    long row2 = (MODE == 0) ? (long)map_row(mBase + ar + 64) : (long)(mBase + ar + 64);
    const __nv_bfloat16* Ap1 = A + row1 * K + ac;
    const __nv_bfloat16* Ap2 = A + row2 * K + ac;
    const unsigned sA1 = aBase + ar * 80 + (t & 3) * 16;
    const unsigned sA2 = sA1 + 64 * 80;
    const int bk = t >> 3;
    const __nv_bfloat16* Bp = Bm + (long)bk * NCOLS + nBase + (t & 7) * 8;
    const unsigned sB = bBase + bk * BROW + (t & 7) * 16;

    float acc[2][NI][4];
    #pragma unroll
    for (int mi = 0; mi < 2; mi++)
        #pragma unroll
        for (int ni = 0; ni < NI; ni++)
            #pragma unroll
            for (int e = 0; e < 4; e++) acc[mi][ni][e] = 0.f;

    const int NK = K / 32;
    #pragma unroll
    for (int s = 0; s < STAGES - 1; s++) {
        cpa16(sA1 + s * A_STAGE, Ap1 + s * 32);
        cpa16(sA2 + s * A_STAGE, Ap2 + s * 32);
        #pragma unroll
        for (int cc = 0; cc < CPT; cc++)
            cpa16(sB + s * B_STAGE + cc * 128, Bp + (long)s * 32 * NCOLS + cc * 64);
        CP_COMMIT();
    }

    for (int kt = 0; kt < NK; kt++) {
        const int s = kt % STAGES;
        if (STAGES == 3) { asm volatile("cp.async.wait_group 1;"); }
        else             { asm volatile("cp.async.wait_group 2;"); }
        __syncthreads();
        if (kt + STAGES - 1 < NK) {
            const int s2 = (kt + STAGES - 1) % STAGES;
            cpa16(sA1 + s2 * A_STAGE, Ap1 + (kt + STAGES - 1) * 32);
            cpa16(sA2 + s2 * A_STAGE, Ap2 + (kt + STAGES - 1) * 32);
            #pragma unroll
            for (int cc = 0; cc < CPT; cc++)
                cpa16(sB + s2 * B_STAGE + cc * 128,
                      Bp + (long)(kt + STAGES - 1) * 32 * NCOLS + cc * 64);
        }
        CP_COMMIT();

        const unsigned as0 = aBase + s * A_STAGE;
        const unsigned bs0 = bBase + s * B_STAGE;
        #pragma unroll
        for (int k16 = 0; k16 < 2; k16++) {
            unsigned af[2][4], bq[G][4];
            #pragma unroll
            for (int mi = 0; mi < 2; mi++)
                ldsm4(af[mi], as0 + (warpM * 32 + mi * 16 + (lane & 15)) * 80
                              + k16 * 32 + (lane >> 4) * 16);
            #pragma unroll
            for (int g = 0; g < G; g++)
                ldsm4t(bq[g], bs0 + (k16 * 16 + (lane & 15)) * BROW
                              + (warpN * (NTILE / 2) + g * 16 + ((lane >> 4) << 3)) * 2);
            #pragma unroll
            for (int mi = 0; mi < 2; mi++)
                #pragma unroll
                for (int ni = 0; ni < NI; ni++)
                    mma_bf16(acc[mi][ni], af[mi], &bq[ni >> 1][(ni & 1) * 2]);
        }
    }

    #pragma unroll
    for (int mi = 0; mi < 2; mi++) {
        int r0 = mBase + warpM * 32 + mi * 16 + lq;
        #pragma unroll
        for (int ni = 0; ni < NI; ni++) {
            int c0 = nBase + warpN * (NTILE / 2) + ni * 8 + lr * 2;
            epi_store<MODE, NCOLS>(r0,     c0,     acc[mi][ni][0], bias, aux, outf, outh);
            epi_store<MODE, NCOLS>(r0,     c0 + 1, acc[mi][ni][1], bias, aux, outf, outh);
            epi_store<MODE, NCOLS>(r0 + 8, c0,     acc[mi][ni][2], bias, aux, outf, outh);
            epi_store<MODE, NCOLS>(r0 + 8, c0 + 1, acc[mi][ni][3], bias, aux, outf, outh);
        }
    }
}

// ---------------------------------------------------------------------------
// One fused conversion pass: x (25165824) then qkv_w|proj_w|fc1_w|fc2_w into
// g_wbf. All segment sizes divisible by 4.
// ---------------------------------------------------------------------------
__global__ void prep_all(const float* __restrict__ x,
                         const float* __restrict__ w0, const float* __restrict__ w1,
                         const float* __restrict__ w2, const float* __restrict__ w3,
                         __nv_bfloat16* __restrict__ xbf, __nv_bfloat16* __restrict__ wbf)
{
    long i = ((long)blockIdx.x * blockDim.x + threadIdx.x) * 4;
    const float* src;
    __nv_bfloat16* dst;
    long o;
    if (i < 25165824) { src = x; dst = xbf; o = i; }
    else {
        long j = i - 25165824;
        if (j < 110592)      { src = w0; dst = wbf;          o = j; }
        else if (j < 147456) { src = w1; dst = wbf + 110592; o = j - 110592; }
        else if (j < 294912) { src = w2; dst = wbf + 147456; o = j - 147456; }
        else if (j < 442368) { src = w3; dst = wbf + 294912; o = j - 294912; }
        else return;
    }
    float4 v = *(const float4*)(src + o);
    *(__nv_bfloat162*)(dst + o)     = __floats2bfloat162_rn(v.x, v.y);
    *(__nv_bfloat162*)(dst + o + 2) = __floats2bfloat162_rn(v.z, v.w);
}

// ---------------------------------------------------------------------------
// Tensor-core attention (unchanged from round 13).
// ---------------------------------------------------------------------------
__global__ __launch_bounds__(128) void attn_kernel(
    const float* __restrict__ rpb, __nv_bfloat16* __restrict__ out)
{
    __shared__ __align__(16) __nv_bfloat16 Qs[64 * 40];
    __shared__ __align__(16) __nv_bfloat16 Ks[64 * 40];
    __shared__ __align__(16) __nv_bfloat16 Vs[64 * 40];

    const int bh = blockIdx.x;
    const int wid = bh / 6, head = bh - wid * 6;
    const int w = wid & 63;
    const int t = threadIdx.x, lane = t & 31, warp = t >> 5;
    const int lq = lane >> 2, lr = lane & 3;

    const unsigned qA = (unsigned)__cvta_generic_to_shared(Qs);
    const unsigned kA = (unsigned)__cvta_generic_to_shared(Ks);
    const unsigned vA = (unsigned)__cvta_generic_to_shared(Vs);
    const __nv_bfloat16* qb = g_qkvh + (long)bh * 2048;

    #pragma unroll
    for (int c = t; c < 256; c += 128) {
        int row = c >> 2, o = c & 3;
        unsigned so = row * 80 + o * 16;
        const __nv_bfloat16* go = qb + row * 32 + o * 8;
        cpa16(qA + so, go);
        cpa16(kA + so, go + QKV_STRIDE);
        cpa16(vA + so, go + 2 * QKV_STRIDE);
    }
    CP_COMMIT();
    CP_WAIT0();
    __syncthreads();

    float sc[8][4];
    #pragma unroll
    for (int ni = 0; ni < 8; ni++)
        #pragma unroll
        for (int e = 0; e < 4; e++) sc[ni][e] = 0.f;

    unsigned af[2][4];
    #pragma unroll
    for (int kc = 0; kc < 2; kc++)
        ldsm4(af[kc], qA + (warp * 16 + (lane & 15)) * 80 + kc * 32 + (lane >> 4) * 16);
    #pragma unroll
    for (int kc = 0; kc < 2; kc++) {
        unsigned bq[4][4];
        #pragma unroll
        for (int g = 0; g < 4; g++)
            ldsm4(bq[g], kA + (g * 16 + (lane & 15)) * 80 + kc * 32 + (lane >> 4) * 16);
        #pragma unroll
        for (int ni = 0; ni < 8; ni++)
            mma_bf16_2(sc[ni], af[kc], bq[ni >> 1][ni & 1], bq[ni >> 1][2 + (ni & 1)]);
    }

    const int hb = (w >> 3) << 3, wbx = (w & 7) << 3;
    const int r0 = warp * 16 + lq, r1 = r0 + 8;
    const int rh0 = r0 >> 3, rw0 = r0 & 7, rh1 = r1 >> 3, rw1 = r1 & 7;
    const int reg0 = region(hb + rh0) * 3 + region(wbx + rw0);
    const int reg1 = region(hb + rh1) * 3 + region(wbx + rw1);
    const int base0 = ((rh0 + 7) * 15 + rw0 + 7) * 6 + head;
    const int base1 = ((rh1 + 7) * 15 + rw1 + 7) * 6 + head;

    float mx0 = -1e30f, mx1 = -1e30f;
    #pragma unroll
    for (int ni = 0; ni < 8; ni++) {
        #pragma unroll
        for (int e = 0; e < 2; e++) {
            int col = ni * 8 + 2 * lr + e;
            int ch = col >> 3, cw = col & 7;
            int cOff = (ch * 15 + cw) * 6;
            int regC = region(hb + ch) * 3 + region(wbx + cw);
            float v0 = sc[ni][e]     + __ldg(rpb + base0 - cOff) + (regC != reg0 ? -100.f : 0.f);
            float v1 = sc[ni][2 + e] + __ldg(rpb + base1 - cOff) + (regC != reg1 ? -100.f : 0.f);
            sc[ni][e] = v0; sc[ni][2 + e] = v1;
            mx0 = fmaxf(mx0, v0); mx1 = fmaxf(mx1, v1);
        }
    }
    mx0 = fmaxf(mx0, __shfl_xor_sync(0xffffffffu, mx0, 1));
    mx0 = fmaxf(mx0, __shfl_xor_sync(0xffffffffu, mx0, 2));
    mx1 = fmaxf(mx1, __shfl_xor_sync(0xffffffffu, mx1, 1));
    mx1 = fmaxf(mx1, __shfl_xor_sync(0xffffffffu, mx1, 2));

    float s0 = 0.f, s1 = 0.f;
    #pragma unroll
    for (int ni = 0; ni < 8; ni++) {
        #pragma unroll
        for (int e = 0; e < 2; e++) {
            float e0 = __expf(sc[ni][e] - mx0);
            float e1 = __expf(sc[ni][2 + e] - mx1);
            sc[ni][e] = e0; sc[ni][2 + e] = e1;
            s0 += e0; s1 += e1;
        }
    }
    s0 += __shfl_xor_sync(0xffffffffu, s0, 1);
    s0 += __shfl_xor_sync(0xffffffffu, s0, 2);
    s1 += __shfl_xor_sync(0xffffffffu, s1, 1);
    s1 += __shfl_xor_sync(0xffffffffu, s1, 2);
    const float inv0 = 1.f / s0, inv1 = 1.f / s1;

    unsigned pa[4][4];
    #pragma unroll
    for (int kc2 = 0; kc2 < 4; kc2++) {
        pa[kc2][0] = pack2(sc[2 * kc2][0],     sc[2 * kc2][1]);
        pa[kc2][1] = pack2(sc[2 * kc2][2],     sc[2 * kc2][3]);
        pa[kc2][2] = pack2(sc[2 * kc2 + 1][0], sc[2 * kc2 + 1][1]);
        pa[kc2][3] = pack2(sc[2 * kc2 + 1][2], sc[2 * kc2 + 1][3]);
    }
    float o4[4][4];
    #pragma unroll
    for (int nf = 0; nf < 4; nf++)
        #pragma unroll
        for (int e = 0; e < 4; e++) o4[nf][e] = 0.f;
    #pragma unroll
    for (int kc2 = 0; kc2 < 4; kc2++) {
        unsigned bv[2][4];
        #pragma unroll
        for (int g2 = 0; g2 < 2; g2++)
            ldsm4t(bv[g2], vA + (kc2 * 16 + (lane & 15)) * 80
                           + (g2 * 16 + ((lane >> 4) << 3)) * 2);
        #pragma unroll
        for (int nf = 0; nf < 4; nf++)
            mma_bf16(o4[nf], pa[kc2], &bv[nf >> 1][2 * (nf & 1)]);
    }

    const long grow = (long)(wid * 64 + r0);
    #pragma unroll
    for (int nf = 0; nf < 4; nf++) {
        int col = head * 32 + nf * 8 + 2 * lr;
        *(__nv_bfloat162*)(out + grow * 192 + col) =
            __floats2bfloat162_rn(o4[nf][0] * inv0, o4[nf][1] * inv0);
        *(__nv_bfloat162*)(out + (grow + 8) * 192 + col) =
            __floats2bfloat162_rn(o4[nf][2] * inv1, o4[nf][3] * inv1);
    }
}

// ---------------------------------------------------------------------------
extern "C" void kernel_launch(void* const* d_in, const int* in_sizes, int n_in,
                              void* d_out, int out_size)
{
    const float* x      = (const float*)d_in[0];
    const float* rpb    = (const float*)d_in[1];
    const float* qkv_w  = (const float*)d_in[2];
    const float* qkv_b  = (const float*)d_in[3];
    const float* proj_w = (const float*)d_in[4];
    const float* proj_b = (const float*)d_in[5];
    const float* fc1_w  = (const float*)d_in[6];
    const float* fc1_b  = (const float*)d_in[7];
    const float* fc2_w  = (const float*)d_in[8];
    const float* fc2_b  = (const float*)d_in[9];
    float* out = (float*)d_out;

    float *x1;
    __nv_bfloat16 *qkvh, *xbf, *att, *x1bf, *h, *wbf;
    cudaGetSymbolAddress((void**)&qkvh, g_qkvh);
    cudaGetSymbolAddress((void**)&xbf,  g_xbf);
    cudaGetSymbolAddress((void**)&att,  g_att);
    cudaGetSymbolAddress((void**)&x1,   g_x1);
    cudaGetSymbolAddress((void**)&x1bf, g_x1bf);
    cudaGetSymbolAddress((void**)&h,    g_h);
    cudaGetSymbolAddress((void**)&wbf,  g_wbf);

    constexpr int SM64_3  = 3 * (A_STAGE + 32 * 144);   // 44544
    constexpr int SM64_4  = 4 * (A_STAGE + 32 * 144);   // 59392
    constexpr int SM128_3 = 3 * (A_STAGE + 32 * 272);   // 56832
    cudaFuncSetAttribute(gemm_bf16<0, 192, 576, 64, 3>,  cudaFuncAttributeMaxDynamicSharedMemorySize, SM64_3);
    cudaFuncSetAttribute(gemm_bf16<1, 192, 192, 64, 3>,  cudaFuncAttributeMaxDynamicSharedMemorySize, SM64_3);
    cudaFuncSetAttribute(gemm_bf16<2, 192, 768, 128, 3>, cudaFuncAttributeMaxDynamicSharedMemorySize, SM128_3);
    cudaFuncSetAttribute(gemm_bf16<3, 768, 192, 64, 4>,  cudaFuncAttributeMaxDynamicSharedMemorySize, SM64_4);

    // one fused conversion pass (x + all weights)
    prep_all<<<(25608192 / 4 + 255) / 256, 256>>>(x, qkv_w, proj_w, fc1_w, fc2_w, xbf, wbf);

    gemm_bf16<0, 192, 576, 64, 3><<<dim3(9, 1024), 256, SM64_3>>>(xbf, wbf, qkv_b, nullptr, nullptr, qkvh);
    attn_kernel<<<12288, 128>>>(rpb, att);
    gemm_bf16<1, 192, 192, 64, 3><<<dim3(3, 1024), 256, SM64_3>>>(att, wbf + 110592, proj_b, x, x1, x1bf);
    gemm_bf16<2, 192, 768, 128, 3><<<dim3(6, 1024), 256, SM128_3>>>(x1bf, wbf + 147456, fc1_b, nullptr, nullptr, h);
    gemm_bf16<3, 768, 192, 64, 4><<<dim3(3, 1024), 256, SM64_4>>>(h, wbf + 294912, fc2_b, x1, out, nullptr);
}

// round 16
// speedup vs baseline: 1.3757x; 1.2689x over previous
#include <cuda_runtime.h>
#include <cuda_bf16.h>
#include <math.h>
#include <stdint.h>

#define NROWS 131072
#define QKV_STRIDE 25165824ll

__device__ __nv_bfloat16 g_qkvh[3ll * 25165824];
__device__ __nv_bfloat16 g_xbf[25165824];
__device__ __nv_bfloat16 g_att[25165824];
__device__ float g_x1[25165824];
__device__ __nv_bfloat16 g_x1bf[25165824];
__device__ __nv_bfloat16 g_h[100663296ll];
__device__ __nv_bfloat16 g_wbf[442368];

__device__ __forceinline__ int map_row(int r) {
    int wid = r >> 6, n = r & 63;
    int b = wid >> 6, w = wid & 63;
    int h  = ((w >> 3) << 3) + (n >> 3);
    int ww = ((w & 7) << 3) + (n & 7);
    int ho = (h + 4) & 63, wo = (ww + 4) & 63;
    return (b << 12) + (ho << 6) + wo;
}
__device__ __forceinline__ int region(int x) { return x < 56 ? 0 : (x < 60 ? 1 : 2); }

__device__ __forceinline__ void cpa16(unsigned s, const void* g) {
    asm volatile("cp.async.cg.shared.global [%0], [%1], 16;" :: "r"(s), "l"(g));
}
#define CP_COMMIT() asm volatile("cp.async.commit_group;")
#define CP_WAIT0()  asm volatile("cp.async.wait_group 0;" ::: "memory")

__device__ __forceinline__ void ldsm4(unsigned* r, unsigned a) {
    asm volatile("ldmatrix.sync.aligned.m8n8.x4.shared.b16 {%0,%1,%2,%3}, [%4];"
        : "=r"(r[0]), "=r"(r[1]), "=r"(r[2]), "=r"(r[3]) : "r"(a));
}
__device__ __forceinline__ void ldsm4t(unsigned* r, unsigned a) {
    asm volatile("ldmatrix.sync.aligned.m8n8.x4.trans.shared.b16 {%0,%1,%2,%3}, [%4];"
        : "=r"(r[0]), "=r"(r[1]), "=r"(r[2]), "=r"(r[3]) : "r"(a));
}
__device__ __forceinline__ void mma_bf16(float* d, const unsigned* a, const unsigned* b) {
    asm volatile(
        "mma.sync.aligned.m16n8k16.row.col.f32.bf16.bf16.f32 "
        "{%0,%1,%2,%3}, {%4,%5,%6,%7}, {%8,%9}, {%0,%1,%2,%3};"
        : "+f"(d[0]), "+f"(d[1]), "+f"(d[2]), "+f"(d[3])
        : "r"(a[0]), "r"(a[1]), "r"(a[2]), "r"(a[3]), "r"(b[0]), "r"(b[1]));
}
__device__ __forceinline__ void mma_bf16_2(float* d, const unsigned* a, unsigned b0, unsigned b1) {
    asm volatile(
        "mma.sync.aligned.m16n8k16.row.col.f32.bf16.bf16.f32 "
        "{%0,%1,%2,%3}, {%4,%5,%6,%7}, {%8,%9}, {%0,%1,%2,%3};"
        : "+f"(d[0]), "+f"(d[1]), "+f"(d[2]), "+f"(d[3])
        : "r"(a[0]), "r"(a[1]), "r"(a[2]), "r"(a[3]), "r"(b0), "r"(b1));
}
__device__ __forceinline__ unsigned pack2(float e, float o) {
    __nv_bfloat162 h = __floats2bfloat162_rn(e, o);
    return *reinterpret_cast<unsigned*>(&h);
}

// ---------------------------------------------------------------------------
// bf16 mma.sync GEMM with smem-staged coalesced epilogue.
// block 128 x NTILE, BK=32, STAGES-deep cp.async pipeline, 8 warps (4M x 2N),
// warp tile 32 x NTILE/2.
// ---------------------------------------------------------------------------
#define A_STAGE 10240   // 128 rows * 80B

template<int MODE, int K, int NCOLS, int NTILE, int STAGES>
__global__ __launch_bounds__(256) void gemm_bf16(
    const __nv_bfloat16* __restrict__ A, const __nv_bfloat16* __restrict__ Bm,
    const float* __restrict__ bias, const float* __restrict__ aux,
    float* __restrict__ outf, __nv_bfloat16* __restrict__ outh)
{
    constexpr int BROW = 2 * NTILE + 16;
    constexpr int B_STAGE = 32 * BROW;
    constexpr int G  = NTILE / 32;
    constexpr int NI = NTILE / 16;
    constexpr int CPT = NTILE / 64;

    extern __shared__ char smem_raw[];
    const unsigned aBase = (unsigned)__cvta_generic_to_shared(smem_raw);
    const unsigned bBase = aBase + STAGES * A_STAGE;

    const int mBase = blockIdx.y * 128;
    const int nBase = blockIdx.x * NTILE;
    const int t = threadIdx.x;
    const int lane = t & 31, warp = t >> 5;
    const int warpM = warp >> 1, warpN = warp & 1;
    const int lq = lane >> 2, lr = lane & 3;

    const int ar = t >> 2;
    const int ac = (t & 3) * 8;
    long row1 = (MODE == 0) ? (long)map_row(mBase + ar)      : (long)(mBase + ar);
    long row2 = (MODE == 0) ? (long)map_row(mBase + ar + 64) : (long)(mBase + ar + 64);
    const __nv_bfloat16* Ap1 = A + row1 * K + ac;
    const __nv_bfloat16* Ap2 = A + row2 * K + ac;
    const unsigned sA1 = aBase + ar * 80 + (t & 3) * 16;
    const unsigned sA2 = sA1 + 64 * 80;
    const int bk = t >> 3;
    const __nv_bfloat16* Bp = Bm + (long)bk * NCOLS + nBase + (t & 7) * 8;
    const unsigned sB = bBase + bk * BROW + (t & 7) * 16;

    float acc[2][NI][4];
    #pragma unroll
    for (int mi = 0; mi < 2; mi++)
        #pragma unroll
        for (int ni = 0; ni < NI; ni++)
            #pragma unroll
            for (int e = 0; e < 4; e++) acc[mi][ni][e] = 0.f;

    const int NK = K / 32;
    #pragma unroll
    for (int s = 0; s < STAGES - 1; s++) {
        cpa16(sA1 + s * A_STAGE, Ap1 + s * 32);
        cpa16(sA2 + s * A_STAGE, Ap2 + s * 32);
        #pragma unroll
        for (int cc = 0; cc < CPT; cc++)
            cpa16(sB + s * B_STAGE + cc * 128, Bp + (long)s * 32 * NCOLS + cc * 64);
        CP_COMMIT();
    }

    for (int kt = 0; kt < NK; kt++) {
        const int s = kt % STAGES;
        if (STAGES == 3) { asm volatile("cp.async.wait_group 1;"); }
        else             { asm volatile("cp.async.wait_group 2;"); }
        __syncthreads();
        if (kt + STAGES - 1 < NK) {
            const int s2 = (kt + STAGES - 1) % STAGES;
            cpa16(sA1 + s2 * A_STAGE, Ap1 + (kt + STAGES - 1) * 32);
            cpa16(sA2 + s2 * A_STAGE, Ap2 + (kt + STAGES - 1) * 32);
            #pragma unroll
            for (int cc = 0; cc < CPT; cc++)
                cpa16(sB + s2 * B_STAGE + cc * 128,
                      Bp + (long)(kt + STAGES - 1) * 32 * NCOLS + cc * 64);
        }
        CP_COMMIT();

        const unsigned as0 = aBase + s * A_STAGE;
        const unsigned bs0 = bBase + s * B_STAGE;
        #pragma unroll
        for (int k16 = 0; k16 < 2; k16++) {
            unsigned af[2][4], bq[G][4];
            #pragma unroll
            for (int mi = 0; mi < 2; mi++)
                ldsm4(af[mi], as0 + (warpM * 32 + mi * 16 + (lane & 15)) * 80
                              + k16 * 32 + (lane >> 4) * 16);
            #pragma unroll
            for (int g = 0; g < G; g++)
                ldsm4t(bq[g], bs0 + (k16 * 16 + (lane & 15)) * BROW
                              + (warpN * (NTILE / 2) + g * 16 + ((lane >> 4) << 3)) * 2);
            #pragma unroll
            for (int mi = 0; mi < 2; mi++)
                #pragma unroll
                for (int ni = 0; ni < NI; ni++)
                    mma_bf16(acc[mi][ni], af[mi], &bq[ni >> 1][(ni & 1) * 2]);
        }
    }

    // ---- smem-staged coalesced epilogue (two half-tile passes) ----
    CP_WAIT0();
    __syncthreads();
    float* Sg = reinterpret_cast<float*>(smem_raw);
    constexpr int SROW = NTILE + 4;
    constexpr int CW = NTILE / 4;          // cols per writeback thread

    #pragma unroll
    for (int p = 0; p < 2; p++) {
        if (p) __syncthreads();
        // stage: compact row = warpM*16 + lq (+8), covering 64 rows
        const int sr = warpM * 16 + lq;
        #pragma unroll
        for (int ni = 0; ni < NI; ni++) {
            int c0 = warpN * (NTILE / 2) + ni * 8 + lr * 2;
            Sg[sr * SROW + c0]           = acc[p][ni][0];
            Sg[sr * SROW + c0 + 1]       = acc[p][ni][1];
            Sg[(sr + 8) * SROW + c0]     = acc[p][ni][2];
            Sg[(sr + 8) * SROW + c0 + 1] = acc[p][ni][3];
        }
        __syncthreads();

        const int i = t >> 2;                               // compact row 0..63
        const int r = mBase + ((i >> 4) << 5) + p * 16 + (i & 15);
        const int cb = (t & 3) * CW;                        // col offset in tile

        float v[CW];
        #pragma unroll
        for (int j = 0; j < CW; j += 4) {
            float4 sv = *(float4*)&Sg[i * SROW + cb + j];
            float4 bv = *(const float4*)&bias[nBase + cb + j];
            v[j] = sv.x + bv.x; v[j + 1] = sv.y + bv.y;
            v[j + 2] = sv.z + bv.z; v[j + 3] = sv.w + bv.w;
        }

        if (MODE == 0) {
            int c = nBase + cb;
            int which = c / 192, rem = c % 192;
            int head = rem >> 5, hd0 = rem & 31;
            float scale = (which == 0) ? 0.17677669529663689f : 1.f;
            unsigned pk[CW / 2];
            #pragma unroll
            for (int j = 0; j < CW; j += 2)
                pk[j / 2] = pack2(v[j] * scale, v[j + 1] * scale);
            __nv_bfloat16* dst = outh + (long)which * QKV_STRIDE +
                ((long)((r >> 6) * 6 + head) * 64 + (r & 63)) * 32 + hd0;
            #pragma unroll
            for (int j = 0; j < CW / 8; j++)
                ((uint4*)dst)[j] = ((uint4*)pk)[j];
        } else if (MODE == 1) {
            long o = (long)map_row(r) * 192 + nBase + cb;
            #pragma unroll
            for (int j = 0; j < CW; j += 4) {
                float4 a4 = *(const float4*)(aux + o + j);
                v[j] += a4.x; v[j + 1] += a4.y; v[j + 2] += a4.z; v[j + 3] += a4.w;
                float4 s4 = make_float4(v[j], v[j + 1], v[j + 2], v[j + 3]);
                *(float4*)(outf + o + j) = s4;
            }
            unsigned pk[CW / 2];
            #pragma unroll
            for (int j = 0; j < CW; j += 2)
                pk[j / 2] = pack2(v[j], v[j + 1]);
            #pragma unroll
            for (int j = 0; j < CW / 8; j++)
                ((uint4*)(outh + o))[j] = ((uint4*)pk)[j];
        } else if (MODE == 2) {
            unsigned pk[CW / 2];
            #pragma unroll
            for (int j = 0; j < CW; j += 2) {
                float g0 = 0.5f * v[j]     * (1.0f + erff(v[j]     * 0.7071067811865476f));
                float g1 = 0.5f * v[j + 1] * (1.0f + erff(v[j + 1] * 0.7071067811865476f));
                pk[j / 2] = pack2(g0, g1);
            }
            __nv_bfloat16* dst = outh + (long)r * NCOLS + nBase + cb;
            #pragma unroll
            for (int j = 0; j < CW / 8; j++)
                ((uint4*)dst)[j] = ((uint4*)pk)[j];
        } else {
            long o = (long)r * NCOLS + nBase + cb;
            #pragma unroll
            for (int j = 0; j < CW; j += 4) {
                float4 a4 = *(const float4*)(aux + o + j);
                float4 s4 = make_float4(v[j] + a4.x, v[j + 1] + a4.y,
                                        v[j + 2] + a4.z, v[j + 3] + a4.w);
                *(float4*)(outf + o + j) = s4;
            }
        }
    }
}

// ---------------------------------------------------------------------------
// One fused conversion pass: x then qkv_w|proj_w|fc1_w|fc2_w.
// ---------------------------------------------------------------------------
__global__ void prep_all(const float* __restrict__ x,
                         const float* __restrict__ w0, const float* __restrict__ w1,
                         const float* __restrict__ w2, const float* __restrict__ w3,
                         __nv_bfloat16* __restrict__ xbf, __nv_bfloat16* __restrict__ wbf)
{
    long i = ((long)blockIdx.x * blockDim.x + threadIdx.x) * 4;
    const float* src;
    __nv_bfloat16* dst;
    long o;
    if (i < 25165824) { src = x; dst = xbf; o = i; }
    else {
        long j = i - 25165824;
        if (j < 110592)      { src = w0; dst = wbf;          o = j; }
        else if (j < 147456) { src = w1; dst = wbf + 110592; o = j - 110592; }
        else if (j < 294912) { src = w2; dst = wbf + 147456; o = j - 147456; }
        else if (j < 442368) { src = w3; dst = wbf + 294912; o = j - 294912; }
        else return;
    }
    float4 v = *(const float4*)(src + o);
    *(__nv_bfloat162*)(dst + o)     = __floats2bfloat162_rn(v.x, v.y);
    *(__nv_bfloat162*)(dst + o + 2) = __floats2bfloat162_rn(v.z, v.w);
}

// ---------------------------------------------------------------------------
// Tensor-core attention (unchanged from round 13).
// ---------------------------------------------------------------------------
__global__ __launch_bounds__(128) void attn_kernel(
    const float* __restrict__ rpb, __nv_bfloat16* __restrict__ out)
{
    __shared__ __align__(16) __nv_bfloat16 Qs[64 * 40];
    __shared__ __align__(16) __nv_bfloat16 Ks[64 * 40];
    __shared__ __align__(16) __nv_bfloat16 Vs[64 * 40];

    const int bh = blockIdx.x;
    const int wid = bh / 6, head = bh - wid * 6;
    const int w = wid & 63;
    const int t = threadIdx.x, lane = t & 31, warp = t >> 5;
    const int lq = lane >> 2, lr = lane & 3;

    const unsigned qA = (unsigned)__cvta_generic_to_shared(Qs);
    const unsigned kA = (unsigned)__cvta_generic_to_shared(Ks);
    const unsigned vA = (unsigned)__cvta_generic_to_shared(Vs);
    const __nv_bfloat16* qb = g_qkvh + (long)bh * 2048;

    #pragma unroll
    for (int c = t; c < 256; c += 128) {
        int row = c >> 2, o = c & 3;
        unsigned so = row * 80 + o * 16;
        const __nv_bfloat16* go = qb + row * 32 + o * 8;
        cpa16(qA + so, go);
        cpa16(kA + so, go + QKV_STRIDE);
        cpa16(vA + so, go + 2 * QKV_STRIDE);
    }
    CP_COMMIT();
    CP_WAIT0();
    __syncthreads();

    float sc[8][4];
    #pragma unroll
    for (int ni = 0; ni < 8; ni++)
        #pragma unroll
        for (int e = 0; e < 4; e++) sc[ni][e] = 0.f;

    unsigned af[2][4];
    #pragma unroll
    for (int kc = 0; kc < 2; kc++)
        ldsm4(af[kc], qA + (warp * 16 + (lane & 15)) * 80 + kc * 32 + (lane >> 4) * 16);
    #pragma unroll
    for (int kc = 0; kc < 2; kc++) {
        unsigned bq[4][4];
        #pragma unroll
        for (int g = 0; g < 4; g++)
            ldsm4(bq[g], kA + (g * 16 + (lane & 15)) * 80 + kc * 32 + (lane >> 4) * 16);
        #pragma unroll
        for (int ni = 0; ni < 8; ni++)
            mma_bf16_2(sc[ni], af[kc], bq[ni >> 1][ni & 1], bq[ni >> 1][2 + (ni & 1)]);
    }

    const int hb = (w >> 3) << 3, wbx = (w & 7) << 3;
    const int r0 = warp * 16 + lq, r1 = r0 + 8;
    const int rh0 = r0 >> 3, rw0 = r0 & 7, rh1 = r1 >> 3, rw1 = r1 & 7;
    const int reg0 = region(hb + rh0) * 3 + region(wbx + rw0);
    const int reg1 = region(hb + rh1) * 3 + region(wbx + rw1);
    const int base0 = ((rh0 + 7) * 15 + rw0 + 7) * 6 + head;
    const int base1 = ((rh1 + 7) * 15 + rw1 + 7) * 6 + head;

    float mx0 = -1e30f, mx1 = -1e30f;
    #pragma unroll
    for (int ni = 0; ni < 8; ni++) {
        #pragma unroll
        for (int e = 0; e < 2; e++) {
            int col = ni * 8 + 2 * lr + e;
            int ch = col >> 3, cw = col & 7;
            int cOff = (ch * 15 + cw) * 6;
            int regC = region(hb + ch) * 3 + region(wbx + cw);
            float v0 = sc[ni][e]     + __ldg(rpb + base0 - cOff) + (regC != reg0 ? -100.f : 0.f);
            float v1 = sc[ni][2 + e] + __ldg(rpb + base1 - cOff) + (regC != reg1 ? -100.f : 0.f);
            sc[ni][e] = v0; sc[ni][2 + e] = v1;
            mx0 = fmaxf(mx0, v0); mx1 = fmaxf(mx1, v1);
        }
    }
    mx0 = fmaxf(mx0, __shfl_xor_sync(0xffffffffu, mx0, 1));
    mx0 = fmaxf(mx0, __shfl_xor_sync(0xffffffffu, mx0, 2));
    mx1 = fmaxf(mx1, __shfl_xor_sync(0xffffffffu, mx1, 1));
    mx1 = fmaxf(mx1, __shfl_xor_sync(0xffffffffu, mx1, 2));

    float s0 = 0.f, s1 = 0.f;
    #pragma unroll
    for (int ni = 0; ni < 8; ni++) {
        #pragma unroll
        for (int e = 0; e < 2; e++) {
            float e0 = __expf(sc[ni][e] - mx0);
            float e1 = __expf(sc[ni][2 + e] - mx1);
            sc[ni][e] = e0; sc[ni][2 + e] = e1;
            s0 += e0; s1 += e1;
        }
    }
    s0 += __shfl_xor_sync(0xffffffffu, s0, 1);
    s0 += __shfl_xor_sync(0xffffffffu, s0, 2);
    s1 += __shfl_xor_sync(0xffffffffu, s1, 1);
    s1 += __shfl_xor_sync(0xffffffffu, s1, 2);
    const float inv0 = 1.f / s0, inv1 = 1.f / s1;

    unsigned pa[4][4];
    #pragma unroll
    for (int kc2 = 0; kc2 < 4; kc2++) {
        pa[kc2][0] = pack2(sc[2 * kc2][0],     sc[2 * kc2][1]);
        pa[kc2][1] = pack2(sc[2 * kc2][2],     sc[2 * kc2][3]);
        pa[kc2][2] = pack2(sc[2 * kc2 + 1][0], sc[2 * kc2 + 1][1]);
        pa[kc2][3] = pack2(sc[2 * kc2 + 1][2], sc[2 * kc2 + 1][3]);
    }
    float o4[4][4];
    #pragma unroll
    for (int nf = 0; nf < 4; nf++)
        #pragma unroll
        for (int e = 0; e < 4; e++) o4[nf][e] = 0.f;
    #pragma unroll
    for (int kc2 = 0; kc2 < 4; kc2++) {
        unsigned bv[2][4];
        #pragma unroll
        for (int g2 = 0; g2 < 2; g2++)
            ldsm4t(bv[g2], vA + (kc2 * 16 + (lane & 15)) * 80
                           + (g2 * 16 + ((lane >> 4) << 3)) * 2);
        #pragma unroll
        for (int nf = 0; nf < 4; nf++)
            mma_bf16(o4[nf], pa[kc2], &bv[nf >> 1][2 * (nf & 1)]);
    }

    const long grow = (long)(wid * 64 + r0);
    #pragma unroll
    for (int nf = 0; nf < 4; nf++) {
        int col = head * 32 + nf * 8 + 2 * lr;
        *(__nv_bfloat162*)(out + grow * 192 + col) =
            __floats2bfloat162_rn(o4[nf][0] * inv0, o4[nf][1] * inv0);
        *(__nv_bfloat162*)(out + (grow + 8) * 192 + col) =
            __floats2bfloat162_rn(o4[nf][2] * inv1, o4[nf][3] * inv1);
    }
}

// ---------------------------------------------------------------------------
extern "C" void kernel_launch(void* const* d_in, const int* in_sizes, int n_in,
                              void* d_out, int out_size)
{
    const float* x      = (const float*)d_in[0];
    const float* rpb    = (const float*)d_in[1];
    const float* qkv_w  = (const float*)d_in[2];
    const float* qkv_b  = (const float*)d_in[3];
    const float* proj_w = (const float*)d_in[4];
    const float* proj_b = (const float*)d_in[5];
    const float* fc1_w  = (const float*)d_in[6];
    const float* fc1_b  = (const float*)d_in[7];
    const float* fc2_w  = (const float*)d_in[8];
    const float* fc2_b  = (const float*)d_in[9];
    float* out = (float*)d_out;

    float *x1;
    __nv_bfloat16 *qkvh, *xbf, *att, *x1bf, *h, *wbf;
    cudaGetSymbolAddress((void**)&qkvh, g_qkvh);
    cudaGetSymbolAddress((void**)&xbf,  g_xbf);
    cudaGetSymbolAddress((void**)&att,  g_att);
    cudaGetSymbolAddress((void**)&x1,   g_x1);
    cudaGetSymbolAddress((void**)&x1bf, g_x1bf);
    cudaGetSymbolAddress((void**)&h,    g_h);
    cudaGetSymbolAddress((void**)&wbf,  g_wbf);

    constexpr int SM64_3  = 3 * (A_STAGE + 32 * 144);   // 44544
    constexpr int SM64_4  = 4 * (A_STAGE + 32 * 144);   // 59392
    constexpr int SM128_3 = 3 * (A_STAGE + 32 * 272);   // 56832
    cudaFuncSetAttribute(gemm_bf16<0, 192, 576, 64, 3>,  cudaFuncAttributeMaxDynamicSharedMemorySize, SM64_3);
    cudaFuncSetAttribute(gemm_bf16<1, 192, 192, 64, 3>,  cudaFuncAttributeMaxDynamicSharedMemorySize, SM64_3);
    cudaFuncSetAttribute(gemm_bf16<2, 192, 768, 128, 3>, cudaFuncAttributeMaxDynamicSharedMemorySize, SM128_3);
    cudaFuncSetAttribute(gemm_bf16<3, 768, 192, 64, 4>,  cudaFuncAttributeMaxDynamicSharedMemorySize, SM64_4);

    prep_all<<<(25608192 / 4 + 255) / 256, 256>>>(x, qkv_w, proj_w, fc1_w, fc2_w, xbf, wbf);

    gemm_bf16<0, 192, 576, 64, 3><<<dim3(9, 1024), 256, SM64_3>>>(xbf, wbf, qkv_b, nullptr, nullptr, qkvh);
    attn_kernel<<<12288, 128>>>(rpb, att);
    gemm_bf16<1, 192, 192, 64, 3><<<dim3(3, 1024), 256, SM64_3>>>(att, wbf + 110592, proj_b, x, x1, x1bf);
    gemm_bf16<2, 192, 768, 128, 3><<<dim3(6, 1024), 256, SM128_3>>>(x1bf, wbf + 147456, fc1_b, nullptr, nullptr, h);
    gemm_bf16<3, 768, 192, 64, 4><<<dim3(3, 1024), 256, SM64_4>>>(h, wbf + 294912, fc2_b, x1, out, nullptr);
}